// round 13
// baseline (speedup 1.0000x reference)
#include <cuda_runtime.h>
#include <math.h>

// Depthwise 5x5 Gaussian blur, separable, barrier-free column streaming with
// packed f32x2 (FFMA2) arithmetic. One warp = one 16-row x 64-col strip;
// lane owns columns 2l,2l+1 carried as a packed 64-bit value. Vertical pass:
// rolling 5-row window (packed); horizontal pass on the vertical sum via
// +-1 lane shuffles then packed FMAs. No smem, no __syncthreads.
// x: [16, 256, 64, 64] f32, sigma: [1] f32.

#define HH 64
#define WW 64
#define TPB 256          // 8 warps = 8 strips per block
#define PD  8            // prefetch distance in rows

typedef unsigned long long u64;

__device__ __forceinline__ u64 pack2(float lo, float hi) {
    u64 r; asm("mov.b64 %0, {%1, %2};" : "=l"(r) : "f"(lo), "f"(hi)); return r;
}
__device__ __forceinline__ void unpack2(float& lo, float& hi, u64 v) {
    asm("mov.b64 {%0, %1}, %2;" : "=f"(lo), "=f"(hi) : "l"(v));
}
__device__ __forceinline__ u64 add2(u64 a, u64 b) {
    u64 r; asm("add.rn.f32x2 %0, %1, %2;" : "=l"(r) : "l"(a), "l"(b)); return r;
}
__device__ __forceinline__ u64 fma2(u64 a, u64 b, u64 c) {
    u64 r; asm("fma.rn.f32x2 %0, %1, %2, %3;" : "=l"(r) : "l"(a), "l"(b), "l"(c)); return r;
}

__global__ __launch_bounds__(TPB) void gauss5_kernel(const float* __restrict__ x,
                                                     const float* __restrict__ sigma_p,
                                                     float* __restrict__ out)
{
    const int tid   = threadIdx.x;
    const int lane  = tid & 31;                        // column pair (2l, 2l+1)
    const int gw    = blockIdx.x * (TPB / 32) + (tid >> 5);
    const int plane = gw >> 2;                         // 0..4095
    const int strip = gw & 3;                          // 16-row strip (0..3)

    const u64* gin  = reinterpret_cast<const u64*>(x)   + (long)plane * 2048;
    u64*       gout = reinterpret_cast<u64*>(out)       + (long)plane * 2048
                                                        + strip * 16 * 32;

    // Gaussian taps (symmetric), center tap folded to 1.
    const float sigma = sigma_p[0];
    const float inv2s2 = 1.0f / (2.0f * sigma * sigma);
    const float g0 = expf(-4.0f * inv2s2);   // |d| = 2
    const float g1 = expf(-1.0f * inv2s2);   // |d| = 1
    const float s1 = 2.0f * (g0 + g1) + 1.0f;
    const float invn = 1.0f / (s1 * s1);
    // fold normalization into the vertical stage
    const u64 VG0 = pack2(g0 * invn, g0 * invn);
    const u64 VG1 = pack2(g1 * invn, g1 * invn);
    const u64 VG2 = pack2(invn, invn);
    const u64 G0  = pack2(g0, g0);
    const u64 G1  = pack2(g1, g1);

    const int row0 = strip * 16 - 2;         // input row held by in[0]

    // in[j] holds input row row0+j (j = 0..19); fully unrolled ring.
    u64 in[20];

    // preload rows 0 .. 4+PD (13 rows)
    #pragma unroll
    for (int j = 0; j < 5 + PD; j++) {
        int r = row0 + j;
        in[j] = (r >= 0 && r < HH) ? gin[r * 32 + lane] : 0ULL;
    }

    #pragma unroll
    for (int rr = 0; rr < 16; rr++) {
        // prefetch row rr + 5 + PD (compile-time bound check)
        if (rr + 5 + PD < 20) {
            const int j = rr + 5 + PD;
            int r = row0 + j;
            in[j] = (r >= 0 && r < HH) ? gin[r * 32 + lane] : 0ULL;
        }

        // vertical pass on rows rr-2 .. rr+2, packed (normalization folded in)
        u64 v = fma2(VG0, add2(in[rr], in[rr + 4]),
                fma2(VG1, add2(in[rr + 1], in[rr + 3]),
                fma2(VG2, in[rr + 2], 0ULL)));

        // horizontal pass on the vertical sum
        float vx, vy;
        unpack2(vx, vy, v);
        float px = __shfl_up_sync(0xffffffffu, vx, 1);    // col 2l-2
        float py = __shfl_up_sync(0xffffffffu, vy, 1);    // col 2l-1
        float nx = __shfl_down_sync(0xffffffffu, vx, 1);  // col 2l+2
        float ny = __shfl_down_sync(0xffffffffu, vy, 1);  // col 2l+3
        if (lane == 0)  { px = 0.0f; py = 0.0f; }         // left zero-pad
        if (lane == 31) { nx = 0.0f; ny = 0.0f; }         // right zero-pad

        // o.x = g0*(px+nx) + g1*(py+vy) + vx
        // o.y = g0*(py+ny) + g1*(vx+nx) + vy
        u64 A = add2(pack2(px, py), pack2(nx, ny));       // (px+nx, py+ny)
        u64 B = add2(pack2(py, vx), pack2(vy, nx));       // (py+vy, vx+nx)
        u64 o = fma2(G0, A, fma2(G1, B, v));

        __stcs(gout + rr * 32 + lane, o);
    }
}

extern "C" void kernel_launch(void* const* d_in, const int* in_sizes, int n_in,
                              void* d_out, int out_size) {
    const float* x = (const float*)d_in[0];
    const float* sigma = (const float*)d_in[1];
    float* out = (float*)d_out;
    int planes = in_sizes[0] / (HH * WW);            // 4096
    int warps  = planes * 4;                         // quarter-plane strips
    gauss5_kernel<<<warps / (TPB / 32), TPB>>>(x, sigma, out);
}

// round 14
// speedup vs baseline: 1.0860x; 1.0860x over previous
#include <cuda_runtime.h>
#include <math.h>

// Depthwise 5x5 Gaussian blur, separable, barrier-free column streaming.
// float4 carriers with 16-lane row segments: one warp = TWO 16-row x 64-col
// strips (segment = lane>>4), lane owns 4 columns. Vertical pass: per-thread
// rolling 5-row window over a software-pipelined row stream (PD=3).
// Horizontal pass on the vertical sum via +-1 lane shuffles (width 16).
// No smem, no __syncthreads. x: [16, 256, 64, 64] f32, sigma: [1] f32.

#define HH 64
#define WW 64
#define TPB 256          // 8 warps = 16 strips per block
#define PD  3            // prefetch distance in rows

__global__ __launch_bounds__(TPB) void gauss5_kernel(const float* __restrict__ x,
                                                     const float* __restrict__ sigma_p,
                                                     float* __restrict__ out)
{
    const int tid  = threadIdx.x;
    const int lane = tid & 31;
    const int qc   = lane & 15;                       // float4 col group (0..15)
    const int seg  = lane >> 4;                       // strip segment (0/1)
    const int gw   = blockIdx.x * (TPB / 32) + (tid >> 5);
    const int strip_g = gw * 2 + seg;                 // global 16-row strip id
    const int plane   = strip_g >> 2;                 // 0..4095
    const int k       = strip_g & 3;                  // strip within plane

    const float4* gin  = reinterpret_cast<const float4*>(x)   + (long)plane * 1024;
    float4*       gout = reinterpret_cast<float4*>(out)       + (long)plane * 1024;

    // Gaussian taps (symmetric), center tap folded to 1.
    const float sigma = sigma_p[0];
    const float inv2s2 = 1.0f / (2.0f * sigma * sigma);
    const float g0 = expf(-4.0f * inv2s2);   // |d| = 2
    const float g1 = expf(-1.0f * inv2s2);   // |d| = 1
    const float s1 = 2.0f * (g0 + g1) + 1.0f;
    const float invn = 1.0f / (s1 * s1);
    // fold normalization into the vertical stage
    const float vg0 = g0 * invn;
    const float vg1 = g1 * invn;
    const float vg2 = invn;

    const int row0 = k * 16 - 2;             // plane row held by in[0]

    // in[j] holds input row row0+j (j = 0..19); fully unrolled ring.
    float4 in[20];
    const float4 Z = make_float4(0.f, 0.f, 0.f, 0.f);

    // preload rows 0 .. 4+PD (8 rows)
    #pragma unroll
    for (int j = 0; j < 5 + PD; j++) {
        int r = row0 + j;
        in[j] = (r >= 0 && r < HH) ? gin[r * 16 + qc] : Z;
    }

    #pragma unroll
    for (int rr = 0; rr < 16; rr++) {
        // prefetch row rr + 5 + PD (compile-time bound check)
        if (rr + 5 + PD < 20) {
            const int j = rr + 5 + PD;
            int r = row0 + j;
            in[j] = (r >= 0 && r < HH) ? gin[r * 16 + qc] : Z;
        }

        // vertical pass on rows rr-2 .. rr+2 (normalization folded in)
        float4 v;
        v.x = vg0 * (in[rr].x + in[rr+4].x) + vg1 * (in[rr+1].x + in[rr+3].x)
            + vg2 * in[rr+2].x;
        v.y = vg0 * (in[rr].y + in[rr+4].y) + vg1 * (in[rr+1].y + in[rr+3].y)
            + vg2 * in[rr+2].y;
        v.z = vg0 * (in[rr].z + in[rr+4].z) + vg1 * (in[rr+1].z + in[rr+3].z)
            + vg2 * in[rr+2].z;
        v.w = vg0 * (in[rr].w + in[rr+4].w) + vg1 * (in[rr+1].w + in[rr+3].w)
            + vg2 * in[rr+2].w;

        // horizontal pass on the vertical sum (16-lane-segment shuffles)
        float pz = __shfl_up_sync(0xffffffffu, v.z, 1, 16);   // col 4c-2
        float pw = __shfl_up_sync(0xffffffffu, v.w, 1, 16);   // col 4c-1
        float nx = __shfl_down_sync(0xffffffffu, v.x, 1, 16); // col 4c+4
        float ny = __shfl_down_sync(0xffffffffu, v.y, 1, 16); // col 4c+5
        if (qc == 0)  { pz = 0.0f; pw = 0.0f; }               // left zero-pad
        if (qc == 15) { nx = 0.0f; ny = 0.0f; }               // right zero-pad

        float4 o;
        o.x = g0 * (pz + v.z) + g1 * (pw + v.y) + v.x;
        o.y = g0 * (pw + v.w) + g1 * (v.x + v.z) + v.y;
        o.z = g0 * (v.x + nx) + g1 * (v.y + v.w) + v.z;
        o.w = g0 * (v.y + ny) + g1 * (v.z + nx) + v.w;
        __stcs(gout + (k * 16 + rr) * 16 + qc, o);
    }
}

extern "C" void kernel_launch(void* const* d_in, const int* in_sizes, int n_in,
                              void* d_out, int out_size) {
    const float* x = (const float*)d_in[0];
    const float* sigma = (const float*)d_in[1];
    float* out = (float*)d_out;
    int planes = in_sizes[0] / (HH * WW);            // 4096
    int warps  = planes * 4 / 2;                     // 2 strips per warp
    gauss5_kernel<<<warps / (TPB / 32), TPB>>>(x, sigma, out);
}

// round 15
// speedup vs baseline: 1.0976x; 1.0107x over previous
#include <cuda_runtime.h>
#include <math.h>

// Depthwise 5x5 Gaussian blur, separable, barrier-free column streaming.
// One warp = one 32-row x 64-col half-plane strip; lane owns 2 columns.
// Vertical pass first (per-thread rolling 5-row window over a software-
// pipelined row stream, prefetch distance PD=6), then horizontal on the
// vertical sum via +-1 lane shuffles. No smem, no __syncthreads.
// x: [16, 256, 64, 64] f32, sigma: [1] f32.

#define HH 64
#define WW 64
#define TPB 256
#define PD  6            // prefetch distance in rows

__global__ __launch_bounds__(TPB) void gauss5_kernel(const float* __restrict__ x,
                                                     const float* __restrict__ sigma_p,
                                                     float* __restrict__ out)
{
    const int tid  = threadIdx.x;
    const int lane = tid & 31;                       // column pair (cols 2l, 2l+1)
    const int gw   = blockIdx.x * (TPB / 32) + (tid >> 5);
    const int plane = gw >> 1;                       // 0..4095
    const int half  = gw & 1;                        // strip: rows 0-31 or 32-63

    const float2* gin  = reinterpret_cast<const float2*>(x)   + (long)plane * 2048;
    float2*       gout = reinterpret_cast<float2*>(out)       + (long)plane * 2048
                                                              + half * 32 * 32;

    // Gaussian taps (symmetric), center tap folded to 1.
    const float sigma = sigma_p[0];
    const float inv2s2 = 1.0f / (2.0f * sigma * sigma);
    const float g0 = expf(-4.0f * inv2s2);   // |d| = 2
    const float g1 = expf(-1.0f * inv2s2);   // |d| = 1
    const float s1 = 2.0f * (g0 + g1) + 1.0f;
    const float invn = 1.0f / (s1 * s1);
    // fold normalization into the vertical stage
    const float vg0 = g0 * invn;
    const float vg1 = g1 * invn;
    const float vg2 = invn;

    const int row0 = half * 32 - 2;          // input row held by in[0]

    // fully unrolled software pipeline: in[j] holds input row row0+j
    float2 in[38];

    #pragma unroll
    for (int j = 0; j < 5 + PD; j++) {
        int r = row0 + j;
        in[j] = (r >= 0 && r < HH) ? gin[r * 32 + lane] : make_float2(0.f, 0.f);
    }

    #pragma unroll
    for (int rr = 0; rr < 32; rr++) {
        // prefetch row rr + 5 + PD (compile-time bound check)
        if (rr + 5 + PD < 5 + PD + 32 - 1 + 1 && rr + 5 + PD < 38) {
            int r = row0 + rr + 5 + PD;
            if (rr + 5 + PD < 36 + PD - 4) { } // no-op; keep structure simple
            in[rr + 5 + PD] = (r >= 0 && r < HH) ? gin[r * 32 + lane]
                                                 : make_float2(0.f, 0.f);
        }

        // vertical pass on rows rr-2 .. rr+2 (normalization folded in)
        float2 v;
        v.x = vg0 * (in[rr].x + in[rr+4].x) + vg1 * (in[rr+1].x + in[rr+3].x)
            + vg2 * in[rr+2].x;
        v.y = vg0 * (in[rr].y + in[rr+4].y) + vg1 * (in[rr+1].y + in[rr+3].y)
            + vg2 * in[rr+2].y;

        // horizontal pass on the vertical sum (in-warp shuffles)
        float px = __shfl_up_sync(0xffffffffu, v.x, 1);    // col 2l-2
        float py = __shfl_up_sync(0xffffffffu, v.y, 1);    // col 2l-1
        float nx = __shfl_down_sync(0xffffffffu, v.x, 1);  // col 2l+2
        float ny = __shfl_down_sync(0xffffffffu, v.y, 1);  // col 2l+3
        if (lane == 0)  { px = 0.0f; py = 0.0f; }          // left zero-pad
        if (lane == 31) { nx = 0.0f; ny = 0.0f; }          // right zero-pad

        float2 o;
        o.x = g0 * (px + nx) + g1 * (py + v.y) + v.x;
        o.y = g0 * (py + ny) + g1 * (v.x + nx) + v.y;
        __stcs(gout + rr * 32 + lane, o);
    }
}

extern "C" void kernel_launch(void* const* d_in, const int* in_sizes, int n_in,
                              void* d_out, int out_size) {
    const float* x = (const float*)d_in[0];
    const float* sigma = (const float*)d_in[1];
    float* out = (float*)d_out;
    int planes = in_sizes[0] / (HH * WW);            // 4096
    int warps  = planes * 2;                         // half-plane strips
    gauss5_kernel<<<warps / (TPB / 32), TPB>>>(x, sigma, out);
}